// round 16
// baseline (speedup 1.0000x reference)
#include <cuda_runtime.h>
#include <cuda_bf16.h>
#include <math.h>

#define BB 4
#define TT 1024
#define DD 256
#define VV 32000
#define NROWS (BB*TT)            // 4096
#define LOGITS_N ((long long)NROWS * VV)   // 131,072,000

typedef unsigned long long u64;

// ---------------- device scratch (no allocations allowed) ----------------
__device__ float g_xp0[NROWS * DD];   // layer0 input projection, row = t*4+b
__device__ float g_rnn[NROWS * DD];   // h1[t] outputs, row = b*1024+t
__device__ float g_final[2 * BB * DD];
__device__ int   g_prog[8];           // per-RNN-CTA completed tick (published)

// ---------------- f32x2 helpers ----------------
__device__ __forceinline__ u64 ffma2(u64 a, u64 b, u64 c) {
    u64 d; asm("fma.rn.f32x2 %0, %1, %2, %3;" : "=l"(d) : "l"(a), "l"(b), "l"(c)); return d;
}
__device__ __forceinline__ u64 dup2(float a) {
    u64 d; asm("mov.b64 %0, {%1, %1};" : "=l"(d) : "f"(a)); return d;
}
__device__ __forceinline__ float red2(u64 a) {
    float lo, hi; asm("mov.b64 {%0, %1}, %2;" : "=f"(lo), "=f"(hi) : "l"(a)); return lo + hi;
}
__device__ __forceinline__ float2 up2(u64 a) {
    float2 r; asm("mov.b64 {%0, %1}, %2;" : "=f"(r.x), "=f"(r.y) : "l"(a)); return r;
}
__device__ __forceinline__ unsigned int smem_u32(const void* p) {
    return (unsigned int)__cvta_generic_to_shared(p);
}
__device__ __forceinline__ void cluster_sync_all() {
    asm volatile("barrier.cluster.arrive.aligned;" ::: "memory");
    asm volatile("barrier.cluster.wait.aligned;"   ::: "memory");
}
__device__ __forceinline__ void st_cluster(unsigned int laddr, int rank, float v) {
    unsigned int ra;
    asm volatile("mapa.shared::cluster.u32 %0, %1, %2;" : "=r"(ra) : "r"(laddr), "r"(rank));
    asm volatile("st.shared::cluster.f32 [%0], %1;" :: "r"(ra), "f"(v) : "memory");
}
__device__ __forceinline__ int ld_acq(const int* p) {
    int v; asm volatile("ld.global.acquire.gpu.s32 %0, [%1];" : "=r"(v) : "l"(p)); return v;
}
__device__ __forceinline__ void st_rel(int* p, int v) {
    asm volatile("st.global.release.gpu.s32 [%0], %1;" :: "l"(p), "r"(v) : "memory");
}

// ===========================================================================
// Kernel 1: embedding gather + x-projection of layer 0 (+ g_prog reset)
// ===========================================================================
__global__ __launch_bounds__(256) void xproj_kernel(
    const int*   __restrict__ ids,
    const float* __restrict__ embed,
    const float* __restrict__ W0,
    const float* __restrict__ b0)
{
    __shared__ __align__(16) float xs_t[DD * 8];
    __shared__ int sid[8];

    const int tid = threadIdx.x;
    const int r0  = blockIdx.x * 8;

    if (blockIdx.x == 0 && tid < 8) g_prog[tid] = 0;   // reset progress each call

    if (tid < 8) {
        int r = r0 + tid;            // row = t*4 + b
        int t = r >> 2, b = r & 3;
        sid[tid] = ids[b * TT + t];
    }
    __syncthreads();

    for (int idx = tid; idx < DD * 8; idx += 256) {
        int j = idx & 7;
        int k = idx >> 3;
        xs_t[idx] = embed[(long long)sid[j] * DD + k];
    }
    __syncthreads();

    const int d = tid;
    const float4* wrow = (const float4*)(W0 + (long long)d * (2 * DD));

    u64 acc[4];
#pragma unroll
    for (int p = 0; p < 4; ++p) acc[p] = 0ULL;

#pragma unroll 8
    for (int kq = 0; kq < DD / 4; ++kq) {
        float4 w4 = wrow[kq];
        const ulonglong2* xp = (const ulonglong2*)(xs_t + (kq * 4) * 8);
        float wk[4] = {w4.x, w4.y, w4.z, w4.w};
#pragma unroll
        for (int c = 0; c < 4; ++c) {
            ulonglong2 x01 = xp[2 * c + 0];
            ulonglong2 x23 = xp[2 * c + 1];
            u64 wd = dup2(wk[c]);
            acc[0] = ffma2(wd, x01.x, acc[0]);
            acc[1] = ffma2(wd, x01.y, acc[1]);
            acc[2] = ffma2(wd, x23.x, acc[2]);
            acc[3] = ffma2(wd, x23.y, acc[3]);
        }
    }
    float bd = b0[d];
#pragma unroll
    for (int p = 0; p < 4; ++p) {
        float2 v = up2(acc[p]);
        g_xp0[(long long)(r0 + 2 * p + 0) * DD + d] = bd + v.x;
        g_xp0[(long long)(r0 + 2 * p + 1) * DD + d] = bd + v.y;
    }
}

// ===========================================================================
// Kernel 2 (FUSED): CTAs 0-7 = RNN cluster; CTAs 8..135 = head GEMM workers
// gated on g_prog. Grid 136 (17 clusters of 8), 512 threads, 1 CTA/SM.
// ===========================================================================
// --- RNN smem layout (floats) ---
#define HCH 68
#define HB  (4 * HCH)                // 272
#define HPAR (BB * HB)               // 1088
#define OFF_H1F (2 * HPAR + 16)      // 2192
#define RNN_SMEM_FLOATS (OFF_H1F + 2 * HPAR)   // 4368
// --- head smem layout ---
#define BM 128
#define BV2 256
#define BK 32
#define AP 132
#define BP 260
#define HEAD_SMEM_FLOATS (BK * AP + BK * BP)   // 4224 + 8320 = 12544
#define POOL_BYTES (HEAD_SMEM_FLOATS * 4)      // 50176 (> RNN's 17472)

#define GRID_FUSED 136
#define NH (GRID_FUSED - 8)          // 128 head CTAs

__global__ __launch_bounds__(512, 1) __cluster_dims__(8, 1, 1)
void fused_kernel(const float* __restrict__ W0,
                  const float* __restrict__ W1,
                  const float* __restrict__ b1,
                  const float* __restrict__ head_w,
                  float* __restrict__ out)
{
    extern __shared__ __align__(16) float pool[];
    const int tid = threadIdx.x;

    if (blockIdx.x < 8) {
        // =================== RNN ROLE ===================
        float* hbuf = pool;
        const int w    = tid >> 5;
        const int l    = tid & 31;
        const int r    = blockIdx.x;
        const int base = r * 32;

        for (int i = tid; i < RNN_SMEM_FLOATS; i += 512) hbuf[i] = 0.0f;

        if (w < 4) {
            // ---- LAYER-0 warps: tick i computes h0[i] ----
            const int dl = w * 8 + (l & 7);
            const int kc = l >> 3;
            const int dg = base + dl;
            const int hpos = (dg >> 6) * HCH + (dg & 63);

            u64 wreg[32];
            {
                const ulonglong2* ws = (const ulonglong2*)(W0 + (long long)dg * 512 + 256 + kc * 64);
#pragma unroll
                for (int j = 0; j < 16; ++j) { ulonglong2 v = ws[j]; wreg[2*j] = v.x; wreg[2*j+1] = v.y; }
            }
            float xp[4] = {0.f, 0.f, 0.f, 0.f};
            if (kc == 0) {
#pragma unroll
                for (int b = 0; b < 4; ++b) xp[b] = g_xp0[(long long)(0 * 4 + b) * DD + dg];
            }

            cluster_sync_all();

            for (int i = 0; i <= TT; ++i) {
                if (i < TT) {
                    const int pr = i & 1;
                    const int pw = pr ^ 1;
                    float xpn[4] = {0.f, 0.f, 0.f, 0.f};
                    if (kc == 0 && i + 1 < TT) {
#pragma unroll
                        for (int b = 0; b < 4; ++b)
                            xpn[b] = g_xp0[(long long)((i + 1) * 4 + b) * DD + dg];
                    }

                    const float* hbase = hbuf + pr * HPAR + kc * HCH;
                    u64 aX[4] = {0,0,0,0}, aY[4] = {0,0,0,0};
#pragma unroll
                    for (int q = 0; q < 16; ++q) {
#pragma unroll
                        for (int b = 0; b < 4; ++b) {
                            ulonglong2 hv = ((const ulonglong2*)(hbase + b * HB))[q];
                            aX[b] = ffma2(wreg[2*q],   hv.x, aX[b]);
                            aY[b] = ffma2(wreg[2*q+1], hv.y, aY[b]);
                        }
                    }
                    float s[4];
#pragma unroll
                    for (int b = 0; b < 4; ++b) {
                        s[b] = red2(aX[b]) + red2(aY[b]) + xp[b];
                        s[b] += __shfl_xor_sync(0xffffffffu, s[b], 8);
                        s[b] += __shfl_xor_sync(0xffffffffu, s[b], 16);
                    }
#pragma unroll
                    for (int b = 0; b < 4; ++b) {
                        float h0v = tanhf(s[b]);
                        unsigned int la = smem_u32(&hbuf[pw * HPAR + b * HB + hpos]);
                        st_cluster(la, 2 * kc + 0, h0v);
                        st_cluster(la, 2 * kc + 1, h0v);
                        if (i == TT - 1 && kc == 0) g_final[b * DD + dg] = h0v;
                    }
#pragma unroll
                    for (int b = 0; b < 4; ++b) xp[b] = xpn[b];
                }
                if ((i & 127) == 0 && i > 0) __threadfence();
                cluster_sync_all();
                if ((i & 127) == 0 && i > 0 && tid == 0) st_rel(&g_prog[r], i);
            }
        } else if (w < 12) {
            // ---- LAYER-1 warps: tick i computes h1[i-1] ----
            const int w1 = w - 4;
            const int dl = w1 * 4 + (l & 3);
            const int kc = l >> 2;
            const int dg = base + dl;
            const int hpos = (dg >> 6) * HCH + (dg & 63);

            u64 wreg[32];
            {
                const ulonglong2* ws = (const ulonglong2*)(W1 + (long long)dg * 512 + kc * 64);
#pragma unroll
                for (int j = 0; j < 16; ++j) { ulonglong2 v = ws[j]; wreg[2*j] = v.x; wreg[2*j+1] = v.y; }
            }
            const float b1v = (kc == 0) ? b1[dg] : 0.0f;

            cluster_sync_all();

            for (int i = 0; i <= TT; ++i) {
                if (i > 0) {
                    const int t    = i - 1;
                    const int ph0  = i & 1;
                    const int ph1r = (i - 1) & 1;
                    const int ph1w = i & 1;

                    const float* hbase = (kc < 4)
                        ? hbuf + ph0 * HPAR + kc * HCH
                        : hbuf + OFF_H1F + ph1r * HPAR + (kc - 4) * HCH;

                    u64 aX[4] = {0,0,0,0}, aY[4] = {0,0,0,0};
#pragma unroll
                    for (int q = 0; q < 16; ++q) {
#pragma unroll
                        for (int b = 0; b < 4; ++b) {
                            ulonglong2 hv = ((const ulonglong2*)(hbase + b * HB))[q];
                            aX[b] = ffma2(wreg[2*q],   hv.x, aX[b]);
                            aY[b] = ffma2(wreg[2*q+1], hv.y, aY[b]);
                        }
                    }
                    float s[4];
#pragma unroll
                    for (int b = 0; b < 4; ++b) {
                        s[b] = red2(aX[b]) + red2(aY[b]) + b1v;
                        s[b] += __shfl_xor_sync(0xffffffffu, s[b], 4);
                        s[b] += __shfl_xor_sync(0xffffffffu, s[b], 8);
                        s[b] += __shfl_xor_sync(0xffffffffu, s[b], 16);
                    }
#pragma unroll
                    for (int b = 0; b < 4; ++b) {
                        float h1v = tanhf(s[b]);
                        unsigned int la = smem_u32(&hbuf[OFF_H1F + ph1w * HPAR + b * HB + hpos]);
                        st_cluster(la, kc, h1v);
                        if (kc == 0) {
                            g_rnn[(long long)(b * TT + t) * DD + dg] = h1v;
                            if (t == TT - 1) g_final[BB * DD + b * DD + dg] = h1v;
                        }
                    }
                }
                if ((i & 127) == 0 && i > 0) __threadfence();
                cluster_sync_all();
            }
        } else {
            // ---- spare warps: mirror the sync pattern only ----
            cluster_sync_all();
            for (int i = 0; i <= TT; ++i) {
                if ((i & 127) == 0 && i > 0) __threadfence();
                cluster_sync_all();
            }
        }
    } else {
        // =================== HEAD-GEMM ROLE ===================
        float* As = pool;                 // [BK][AP]
        float* Bs = pool + BK * AP;       // [BK][BP]
        const int hc = blockIdx.x - 8;    // 0..NH-1

        const int tm = tid >> 5;          // 0..15 (8 m-rows each)
        const int tv = tid & 31;          // 0..31 (8 v-cols each)
        const int lkq = tid & 7;          // loader: k-quad
        const int lr  = tid >> 3;         // loader: row 0..63

        for (int p = 0; p < 8; ++p) {
            // wait until h1[t] ready for all t < 128*(p+1)
            if (tid == 0) {
                const int need = 128 * (p + 1);
                long long spins = 0;
                while (true) {
                    int mn = ld_acq(&g_prog[0]);
#pragma unroll
                    for (int rr = 1; rr < 8; ++rr) {
                        int v = ld_acq(&g_prog[rr]);
                        mn = v < mn ? v : mn;
                    }
                    if (mn >= need) break;
                    __nanosleep(256);
                    if (++spins > 8000000LL) break;   // bounded fallback (~2s)
                }
            }
            __syncthreads();

            for (int idx = hc; idx < 4 * 125; idx += NH) {
                const int bb = idx / 125;          // batch 0..3
                const int vt = idx % 125;          // v-tile 0..124
                const long long mBase = (long long)bb * 1024 + (long long)p * 128;
                const long long vBase = (long long)vt * BV2;

                u64 acc[8][4];
#pragma unroll
                for (int mi = 0; mi < 8; ++mi)
#pragma unroll
                    for (int vp = 0; vp < 4; ++vp) acc[mi][vp] = 0ULL;

                for (int kcc = 0; kcc < DD; kcc += BK) {
#pragma unroll
                    for (int i2 = 0; i2 < 2; ++i2) {
                        int m = lr + 64 * i2;
                        float4 av = *(const float4*)(g_rnn + (mBase + m) * DD + kcc + lkq * 4);
                        As[(lkq * 4 + 0) * AP + m] = av.x;
                        As[(lkq * 4 + 1) * AP + m] = av.y;
                        As[(lkq * 4 + 2) * AP + m] = av.z;
                        As[(lkq * 4 + 3) * AP + m] = av.w;
                    }
#pragma unroll
                    for (int i2 = 0; i2 < 4; ++i2) {
                        int v = lr + 64 * i2;
                        float4 bv = *(const float4*)(head_w + (vBase + v) * DD + kcc + lkq * 4);
                        Bs[(lkq * 4 + 0) * BP + v] = bv.x;
                        Bs[(lkq * 4 + 1) * BP + v] = bv.y;
                        Bs[(lkq * 4 + 2) * BP + v] = bv.z;
                        Bs[(lkq * 4 + 3) * BP + v] = bv.w;
                    }
                    __syncthreads();

#pragma unroll 8
                    for (int k = 0; k < BK; ++k) {
                        const float4* ap = (const float4*)(As + k * AP + tm * 8);
                        float4 a0 = ap[0], a1 = ap[1];
                        const ulonglong2* bp = (const ulonglong2*)(Bs + k * BP + tv * 8);
                        ulonglong2 bq0 = bp[0], bq1 = bp[1];
                        u64 bv0 = bq0.x, bv1 = bq0.y, bv2 = bq1.x, bv3 = bq1.y;
                        float am[8] = {a0.x, a0.y, a0.z, a0.w, a1.x, a1.y, a1.z, a1.w};
#pragma unroll
                        for (int mi = 0; mi < 8; ++mi) {
                            u64 ad = dup2(am[mi]);
                            acc[mi][0] = ffma2(ad, bv0, acc[mi][0]);
                            acc[mi][1] = ffma2(ad, bv1, acc[mi][1]);
                            acc[mi][2] = ffma2(ad, bv2, acc[mi][2]);
                            acc[mi][3] = ffma2(ad, bv3, acc[mi][3]);
                        }
                    }
                    __syncthreads();
                }

                const long long vOut = vBase + tv * 8;
#pragma unroll
                for (int mi = 0; mi < 8; ++mi) {
                    long long row = mBase + tm * 8 + mi;
                    float2 p0 = up2(acc[mi][0]);
                    float2 p1 = up2(acc[mi][1]);
                    float2 p2 = up2(acc[mi][2]);
                    float2 p3 = up2(acc[mi][3]);
                    float4 o0 = make_float4(p0.x, p0.y, p1.x, p1.y);
                    float4 o1 = make_float4(p2.x, p2.y, p3.x, p3.y);
                    float* dst = out + row * VV + vOut;
                    *(float4*)(dst + 0) = o0;
                    *(float4*)(dst + 4) = o1;
                }
            }
        }
    }
}

// ===========================================================================
// Kernel 3: append final_hidden after logits if the output has room.
// ===========================================================================
__global__ void tail_kernel(float* __restrict__ out, int n)
{
    int i = blockIdx.x * blockDim.x + threadIdx.x;
    if (i < n) out[LOGITS_N + i] = g_final[i];
}

// ===========================================================================
extern "C" void kernel_launch(void* const* d_in, const int* in_sizes, int n_in,
                              void* d_out, int out_size)
{
    const int*   ids    = (const int*)  d_in[0];
    const float* embed  = (const float*)d_in[1];
    const float* W0     = (const float*)d_in[2];
    const float* b0     = (const float*)d_in[3];
    const float* W1     = (const float*)d_in[4];
    const float* b1     = (const float*)d_in[5];
    const float* head_w = (const float*)d_in[6];
    float* out = (float*)d_out;

    cudaFuncSetAttribute(fused_kernel, cudaFuncAttributeMaxDynamicSharedMemorySize,
                         POOL_BYTES);

    xproj_kernel<<<NROWS / 8, 256>>>(ids, embed, W0, b0);
    fused_kernel<<<GRID_FUSED, 512, POOL_BYTES>>>(W0, W1, b1, head_w, out);

    long long extra = (long long)out_size - LOGITS_N;
    if (extra > 0) {
        int n = (int)(extra < 2LL * BB * DD ? extra : 2LL * BB * DD);
        tail_kernel<<<(n + 255) / 256, 256>>>(out, n);
    }
}